// round 15
// baseline (speedup 1.0000x reference)
#include <cuda_runtime.h>
#include <cuda_fp16.h>
#include <cstdint>

// ============================================================================
// IntraSentenceAttention, flash-style, fp16 mma.sync m16n8k16 + ldmatrix,
// one-tile software pipelining (phase B of jt-1, then phase A of jt).
// Epilogue in the exp2 domain, specialized PER WARP by tile position:
//   j0 <= iw0-73 : dist ≡ 10      -> 2 ops/element
//   j0 >= iw0+5  : dist = i-j     -> 3 ops/element (no clamp)
//   otherwise    : general clamp  -> 4 ops/element
//   S = Xi·Xjᵀ   (A=Xi ldmatrix, B=Xj ldmatrix non-trans; k = d)
//   P = exp(S + min(i-j,10) + logmask)   -> packed fp16 regs (in-place pk)
//   O += P·Xj    (A=P registers, B=Xj ldmatrix TRANS; k = j)
// B=32, T=1024, D=128. CTA 128 i-rows, 16 j-tiles of 64, 256 thr / 8 warps,
// 2 CTAs/SM. Xj triple-buffered.
// ============================================================================

namespace {
constexpr int Bb = 32, Tt = 1024, Dd = 128;
constexpr int TM = 128, TN = 64;
constexpr int NJT = Tt / TN;             // 16
constexpr float EPSF = 1e-7f;
constexpr float NEG_INF = -1e30f;
constexpr float L2E = 1.44269504088896f; // log2(e)
constexpr float C10 = 14.4269504088896f; // 10*log2(e)

constexpr int PX = 272;                  // Xi/Xj row pitch bytes, ≡16 mod 128
constexpr int XJSZ = TN * PX;            // 17408

// SMEM byte offsets
constexpr int SM_XI  = 0;                        // 128*272 = 34816
constexpr int SM_XJ  = 34816;                    // 3 x 17408 = 52224
constexpr int SM_LM  = 87040;                    // 1024 f log-mask (4 KB)
constexpr int SM_RP  = 91136;                    // 128 f
constexpr int SM_INV = 91648;                    // 128 f
constexpr int SMEM_BYTES = 92160;                // 2 CTAs/SM
}

__device__ uint4 g_x16[Bb * Tt * Dd / 8];   // x as fp16, [b][t][d] row-major
__device__ int   g_flags[2];                // zero-init; atomicOr of input-derived bits
                                            // => idempotent across calls/replays

// fp16 convert over all of x (2 float4 -> 1 uint4 per thread);
// blocks 0..31 additionally scan the mask words.
__global__ void cvt16_detect_kernel(const float4* __restrict__ x,
                                    const unsigned int* __restrict__ mw) {
    int i = blockIdx.x * 256 + threadIdx.x;
    float4 v0 = x[2 * i], v1 = x[2 * i + 1];
    __half2 h0 = __floats2half2_rn(v0.x, v0.y);
    __half2 h1 = __floats2half2_rn(v0.z, v0.w);
    __half2 h2 = __floats2half2_rn(v1.x, v1.y);
    __half2 h3 = __floats2half2_rn(v1.z, v1.w);
    g_x16[i] = make_uint4(*(const uint32_t*)&h0, *(const uint32_t*)&h1,
                          *(const uint32_t*)&h2, *(const uint32_t*)&h3);

    if (blockIdx.x < 32) {
        int wi = blockIdx.x * 256 + threadIdx.x;
        int not_int = 0, not_flt = 0;
        if (wi < (Bb * Tt) / 4) {
            unsigned wv = mw[wi];
            if (wv > 1u) not_int = 1;
            if (wv != 0u && wv != 0x3F800000u) not_flt = 1;
        }
        if (__ballot_sync(0xffffffffu, not_int) && (threadIdx.x & 31) == 0)
            atomicOr(&g_flags[0], 1);
        if (__ballot_sync(0xffffffffu, not_flt) && (threadIdx.x & 31) == 0)
            atomicOr(&g_flags[1], 1);
    }
}

__device__ __forceinline__ float get_mask(const void* m, int idx, int mode) {
    if (mode == 1) return ((const int*)m)[idx] ? 1.0f : 0.0f;
    if (mode == 2) return ((const float*)m)[idx];
    return ((const unsigned char*)m)[idx] ? 1.0f : 0.0f;
}

__device__ __forceinline__ uint32_t smem_u32(const void* p) {
    uint32_t a;
    asm("{ .reg .u64 t; cvta.to.shared.u64 t, %1; cvt.u32.u64 %0, t; }" : "=r"(a) : "l"(p));
    return a;
}
__device__ __forceinline__ void cp16(uint32_t dst, const void* src) {
    asm volatile("cp.async.cg.shared.global [%0], [%1], 16;" :: "r"(dst), "l"(src));
}
#define CP_COMMIT() asm volatile("cp.async.commit_group;" ::: "memory")
#define CP_WAIT0()  asm volatile("cp.async.wait_group 0;" ::: "memory")

__device__ __forceinline__ void ldsm4(uint32_t r[4], uint32_t a) {
    asm volatile("ldmatrix.sync.aligned.m8n8.x4.shared.b16 {%0,%1,%2,%3}, [%4];"
                 : "=r"(r[0]), "=r"(r[1]), "=r"(r[2]), "=r"(r[3]) : "r"(a));
}
__device__ __forceinline__ void ldsm4t(uint32_t r[4], uint32_t a) {
    asm volatile("ldmatrix.sync.aligned.m8n8.x4.trans.shared.b16 {%0,%1,%2,%3}, [%4];"
                 : "=r"(r[0]), "=r"(r[1]), "=r"(r[2]), "=r"(r[3]) : "r"(a));
}
__device__ __forceinline__ void mma_f16(float d[4], uint32_t a0, uint32_t a1,
                                        uint32_t a2, uint32_t a3,
                                        uint32_t b0, uint32_t b1) {
    asm volatile(
        "mma.sync.aligned.m16n8k16.row.col.f32.f16.f16.f32 "
        "{%0,%1,%2,%3}, {%4,%5,%6,%7}, {%8,%9}, {%0,%1,%2,%3};"
        : "+f"(d[0]), "+f"(d[1]), "+f"(d[2]), "+f"(d[3])
        : "r"(a0), "r"(a1), "r"(a2), "r"(a3), "r"(b0), "r"(b1));
}
__device__ __forceinline__ float ex2f(float v) {
    float r;
    asm("ex2.approx.ftz.f32 %0, %1;" : "=f"(r) : "f"(v));
    return r;
}

// ---------------------------------------------------------------- main kernel
__global__ __launch_bounds__(256, 2)
void attn_mma(const void* __restrict__ mask, float* __restrict__ out) {
    extern __shared__ char sm[];
    const uint32_t sb = smem_u32(sm);

    const int tid  = threadIdx.x;
    const int w    = tid >> 5, lane = tid & 31;
    const int qrow = lane >> 2;       // 0..7
    const int qk   = lane & 3;        // 0..3
    const int arow0 = w * 16;         // this warp's 16-row band

    const int b  = blockIdx.y;
    const int i0 = blockIdx.x * TM;
    const int mode = (!g_flags[0]) ? 1 : ((!g_flags[1]) ? 2 : 0);
    const char* gx = (const char*)g_x16;     // fp16 x, 256B per row

    // ldmatrix lane-address offsets (bytes; per-ks/nb terms added at use)
    const int l7 = lane & 7, l8 = (lane >> 3) & 1, l16 = (lane >> 4) & 1;
    const uint32_t offA_xi = (uint32_t)((arow0 + l7 + 8 * l8) * PX + l16 * 16);
    const uint32_t offB_A  = (uint32_t)((l7 + 8 * l16) * PX + l8 * 16);
    const uint32_t offB_B  = (uint32_t)((l7 + 8 * l8) * PX + (8 * l16) * 2);

    float* sLM = (float*)(sm + SM_LM);

    // ---- stage Xi (cp.async) + tile-0 Xj + log-mask table ----
    {
        const int xr = tid >> 1;                          // 0..127
        const size_t srow = (size_t)(b * Tt + i0 + xr) * 256;
        #pragma unroll
        for (int i = 0; i < 8; i++) {
            const int ch = (tid & 1) + 2 * i;
            cp16(sb + SM_XI + xr * PX + ch * 16, gx + srow + ch * 16);
        }
        const int jr = tid >> 2;                          // 0..63
        const size_t jrow = (size_t)(b * Tt + jr) * 256;
        #pragma unroll
        for (int i = 0; i < 4; i++) {
            const int ch = (tid & 3) + 4 * i;
            cp16(sb + SM_XJ + jr * PX + ch * 16, gx + jrow + ch * 16);
        }
        CP_COMMIT();
    }
    #pragma unroll
    for (int e = 0; e < 4; e++) {
        const int t = tid + 256 * e;
        sLM[t] = (get_mask(mask, b * Tt + t, mode) != 0.0f) ? 0.0f : NEG_INF;
    }

    float acc[16][4];                 // O: 16 rows x 128 cols per warp
    #pragma unroll
    for (int nf = 0; nf < 16; nf++)
        #pragma unroll
        for (int c = 0; c < 4; c++) acc[nf][c] = 0.0f;
    float rsum[2] = {0.f, 0.f};       // rows qrow, qrow+8

    uint32_t pkp01[8], pkp23[8];      // P fragments (phase-B A-operand)
    const float qk2f = (float)(2 * qk);
    const int iw0 = i0 + arow0;       // warp's global row base

    // prefetch tile jt+1 into buffer (jt+1)%3 (pure cp.async)
    auto prefetch = [&](int jt) {
        const uint32_t dst = sb + SM_XJ + ((jt + 1) % 3) * XJSZ;
        const int jr = tid >> 2;
        const size_t jrow = (size_t)(b * Tt + (jt + 1) * TN + jr) * 256;
        #pragma unroll
        for (int i = 0; i < 4; i++) {
            const int ch = (tid & 3) + 4 * i;
            cp16(dst + jr * PX + ch * 16, gx + jrow + ch * 16);
        }
        CP_COMMIT();
    };

    // phase A: S = Xi.Xj^T for tile jt (accumulators in s)
    auto phaseA = [&](int jt, float s[8][4]) {
        const uint32_t xjb = sb + SM_XJ + (jt % 3) * XJSZ;
        #pragma unroll
        for (int ks = 0; ks < Dd / 16; ++ks) {
            uint32_t a[4];
            ldsm4(a, sb + SM_XI + offA_xi + ks * 32);
            #pragma unroll
            for (int nb = 0; nb < 4; nb++) {
                uint32_t bb[4];
                ldsm4(bb, xjb + offB_A + nb * 16 * PX + ks * 32);
                mma_f16(s[2 * nb],     a[0], a[1], a[2], a[3], bb[0], bb[1]);
                mma_f16(s[2 * nb + 1], a[0], a[1], a[2], a[3], bb[2], bb[3]);
            }
        }
    };

    // epilogue: P = ex2(s*L2E + distL + lmL), per-warp specialized;
    // writes packed fp16 OVER pkp (fully consumed by the preceding phase B).
    auto epilogue = [&](int jt, float s[8][4]) {
        const int j0 = jt * TN;
        const float* lmj = sLM + j0;
        if (j0 <= iw0 - 73) {
            // dist == 10 over the warp's whole 16x64 region
            #pragma unroll
            for (int nf = 0; nf < 8; nf++) {
                const float2 lm = *(const float2*)(lmj + nf * 8 + 2 * qk);
                const float c0 = lm.x + C10, c1 = lm.y + C10;
                float p0 = ex2f(fmaf(s[nf][0], L2E, c0));
                float p1 = ex2f(fmaf(s[nf][1], L2E, c1));
                float p2 = ex2f(fmaf(s[nf][2], L2E, c0));
                float p3 = ex2f(fmaf(s[nf][3], L2E, c1));
                rsum[0] += p0 + p1;
                rsum[1] += p2 + p3;
                __half2 h01 = __floats2half2_rn(p0, p1);
                __half2 h23 = __floats2half2_rn(p2, p3);
                pkp01[nf] = *(const uint32_t*)&h01;
                pkp23[nf] = *(const uint32_t*)&h23;
            }
        } else if (j0 >= iw0 + 5) {
            // max i-j = iw0+15-j0 <= 10: clamp degenerate, dist = i-j
            const float fqL = ((float)(iw0 + qrow - j0) - qk2f) * L2E;
            #pragma unroll
            for (int nf = 0; nf < 8; nf++) {
                const float2 lm = *(const float2*)(lmj + nf * 8 + 2 * qk);
                const float dL = fqL - (float)(nf * 8) * L2E;
                const float a0 = dL + lm.x,             a1 = dL - L2E + lm.y;
                const float a2 = dL + 8.f * L2E + lm.x, a3 = dL + 7.f * L2E + lm.y;
                float p0 = ex2f(fmaf(s[nf][0], L2E, a0));
                float p1 = ex2f(fmaf(s[nf][1], L2E, a1));
                float p2 = ex2f(fmaf(s[nf][2], L2E, a2));
                float p3 = ex2f(fmaf(s[nf][3], L2E, a3));
                rsum[0] += p0 + p1;
                rsum[1] += p2 + p3;
                __half2 h01 = __floats2half2_rn(p0, p1);
                __half2 h23 = __floats2half2_rn(p2, p3);
                pkp01[nf] = *(const uint32_t*)&h01;
                pkp23[nf] = *(const uint32_t*)&h23;
            }
        } else {
            // general: dist = min(i-j, 10), computed in the log2 domain
            const float fqL = ((float)(iw0 + qrow - j0) - qk2f) * L2E;
            #pragma unroll
            for (int nf = 0; nf < 8; nf++) {
                const float2 lm = *(const float2*)(lmj + nf * 8 + 2 * qk);
                const float dL = fqL - (float)(nf * 8) * L2E;
                const float m0 = fminf(dL,             C10) + lm.x;
                const float m1 = fminf(dL - L2E,       C10) + lm.y;
                const float m2 = fminf(dL + 8.f * L2E, C10) + lm.x;
                const float m3 = fminf(dL + 7.f * L2E, C10) + lm.y;
                float p0 = ex2f(fmaf(s[nf][0], L2E, m0));
                float p1 = ex2f(fmaf(s[nf][1], L2E, m1));
                float p2 = ex2f(fmaf(s[nf][2], L2E, m2));
                float p3 = ex2f(fmaf(s[nf][3], L2E, m3));
                rsum[0] += p0 + p1;
                rsum[1] += p2 + p3;
                __half2 h01 = __floats2half2_rn(p0, p1);
                __half2 h23 = __floats2half2_rn(p2, p3);
                pkp01[nf] = *(const uint32_t*)&h01;
                pkp23[nf] = *(const uint32_t*)&h23;
            }
        }
    };

    // phase B: O += P(prev tile) . Xj(prev tile); A-operand from pk registers
    auto phaseB = [&](int jtprev) {
        const uint32_t xjb = sb + SM_XJ + (jtprev % 3) * XJSZ;
        #pragma unroll
        for (int ks = 0; ks < TN / 16; ++ks) {
            const uint32_t a0 = pkp01[2 * ks], a1 = pkp23[2 * ks];
            const uint32_t a2 = pkp01[2 * ks + 1], a3 = pkp23[2 * ks + 1];
            #pragma unroll
            for (int nb = 0; nb < 8; nb++) {
                uint32_t bb[4];
                ldsm4t(bb, xjb + offB_B + nb * 32 + ks * 16 * PX);
                mma_f16(acc[2 * nb],     a0, a1, a2, a3, bb[0], bb[1]);
                mma_f16(acc[2 * nb + 1], a0, a1, a2, a3, bb[2], bb[3]);
            }
        }
    };

    // ---- pipelined main loop ----
    CP_WAIT0();
    __syncthreads();
    prefetch(0);
    {
        float s[8][4];
        #pragma unroll
        for (int nf = 0; nf < 8; nf++)
            #pragma unroll
            for (int c = 0; c < 4; c++) s[nf][c] = 0.0f;
        phaseA(0, s);
        epilogue(0, s);
    }

    for (int jt = 1; jt < NJT; ++jt) {
        CP_WAIT0();
        __syncthreads();   // buf jt ready; everyone done with buf (jt+1)%3 == (jt-2)%3
        if (jt + 1 < NJT) prefetch(jt);

        phaseB(jt - 1);    // consumes pkp

        float s[8][4];
        #pragma unroll
        for (int nf = 0; nf < 8; nf++)
            #pragma unroll
            for (int c = 0; c < 4; c++) s[nf][c] = 0.0f;
        phaseA(jt, s);
        epilogue(jt, s);   // overwrites pkp in place
    }
    phaseB(NJT - 1);       // drain

    // ---- row-sum reduction + inverse (each row owned by exactly one warp) ----
    float* sRP  = (float*)(sm + SM_RP);
    float* sInv = (float*)(sm + SM_INV);
    #pragma unroll
    for (int rh = 0; rh < 2; rh++) {
        float v = rsum[rh];
        v += __shfl_xor_sync(0xffffffffu, v, 1);
        v += __shfl_xor_sync(0xffffffffu, v, 2);
        if (qk == 0) sRP[arow0 + rh * 8 + qrow] = v;
    }
    __syncthreads();
    if (tid < TM)
        sInv[tid] = ((sLM[i0 + tid] == 0.0f) ? 1.0f : 0.0f) / (sRP[tid] + EPSF);
    __syncthreads();

    // ---- write O ----
    {
        const int rl0 = arow0 + qrow;
        const float inv0 = sInv[rl0], inv1 = sInv[rl0 + 8];
        float* o0 = out + ((size_t)b * Tt + i0 + rl0) * Dd;
        float* o1 = o0 + 8 * Dd;
        #pragma unroll
        for (int nf = 0; nf < 16; nf++) {
            const int cl = nf * 8 + 2 * qk;
            *(float2*)(o0 + cl) = make_float2(acc[nf][0] * inv0, acc[nf][1] * inv0);
            *(float2*)(o1 + cl) = make_float2(acc[nf][2] * inv1, acc[nf][3] * inv1);
        }
    }
}

extern "C" void kernel_launch(void* const* d_in, const int* in_sizes, int n_in,
                              void* d_out, int out_size) {
    const float* x   = (const float*)d_in[0];
    const void* mask = d_in[1];
    float* out       = (float*)d_out;

    cudaFuncSetAttribute(attn_mma, cudaFuncAttributeMaxDynamicSharedMemorySize, SMEM_BYTES);

    cvt16_detect_kernel<<<(Bb * Tt * Dd / 8) / 256, 256>>>(
        (const float4*)x, (const unsigned int*)mask);
    dim3 grid(Tt / TM, Bb);
    attn_mma<<<grid, 256, SMEM_BYTES>>>(mask, out);
}

// round 16
// speedup vs baseline: 1.5234x; 1.5234x over previous
#include <cuda_runtime.h>
#include <cuda_fp16.h>
#include <cstdint>

// ============================================================================
// IntraSentenceAttention, flash-style, fp16 mma.sync m16n8k16 + ldmatrix,
// one-tile software pipelining (phase B of jt-1, then phase A of jt).
// Epilogue in the exp2 domain, specialized by tile position with
// BLOCK-UNIFORM thresholds (per-warp thresholds cause ptxas to spill the pk
// arrays to local memory -- R15 regression):
//   j0 <= i0-73  : dist ≡ 10      -> 2 ops/element
//   j0 >= i0+117 : dist = i-j     -> 3 ops/element (no clamp)
//   otherwise    : general clamp  -> 4 ops/element
//   S = Xi·Xjᵀ   (A=Xi ldmatrix, B=Xj ldmatrix non-trans; k = d)
//   P = exp(S + min(i-j,10) + logmask)   -> packed fp16 regs (in-place pk)
//   O += P·Xj    (A=P registers, B=Xj ldmatrix TRANS; k = j)
// B=32, T=1024, D=128. CTA 128 i-rows, 16 j-tiles of 64, 256 thr / 8 warps,
// 2 CTAs/SM. Xj triple-buffered.
// ============================================================================

namespace {
constexpr int Bb = 32, Tt = 1024, Dd = 128;
constexpr int TM = 128, TN = 64;
constexpr int NJT = Tt / TN;             // 16
constexpr float EPSF = 1e-7f;
constexpr float NEG_INF = -1e30f;
constexpr float L2E = 1.44269504088896f; // log2(e)
constexpr float C10 = 14.4269504088896f; // 10*log2(e)

constexpr int PX = 272;                  // Xi/Xj row pitch bytes, ≡16 mod 128
constexpr int XJSZ = TN * PX;            // 17408

// SMEM byte offsets
constexpr int SM_XI  = 0;                        // 128*272 = 34816
constexpr int SM_XJ  = 34816;                    // 3 x 17408 = 52224
constexpr int SM_LM  = 87040;                    // 1024 f log-mask (4 KB)
constexpr int SM_RP  = 91136;                    // 128 f
constexpr int SM_INV = 91648;                    // 128 f
constexpr int SMEM_BYTES = 92160;                // 2 CTAs/SM
}

__device__ uint4 g_x16[Bb * Tt * Dd / 8];   // x as fp16, [b][t][d] row-major
__device__ int   g_flags[2];                // zero-init; atomicOr of input-derived bits
                                            // => idempotent across calls/replays

// fp16 convert over all of x (2 float4 -> 1 uint4 per thread);
// blocks 0..31 additionally scan the mask words.
__global__ void cvt16_detect_kernel(const float4* __restrict__ x,
                                    const unsigned int* __restrict__ mw) {
    int i = blockIdx.x * 256 + threadIdx.x;
    float4 v0 = x[2 * i], v1 = x[2 * i + 1];
    __half2 h0 = __floats2half2_rn(v0.x, v0.y);
    __half2 h1 = __floats2half2_rn(v0.z, v0.w);
    __half2 h2 = __floats2half2_rn(v1.x, v1.y);
    __half2 h3 = __floats2half2_rn(v1.z, v1.w);
    g_x16[i] = make_uint4(*(const uint32_t*)&h0, *(const uint32_t*)&h1,
                          *(const uint32_t*)&h2, *(const uint32_t*)&h3);

    if (blockIdx.x < 32) {
        int wi = blockIdx.x * 256 + threadIdx.x;
        int not_int = 0, not_flt = 0;
        if (wi < (Bb * Tt) / 4) {
            unsigned wv = mw[wi];
            if (wv > 1u) not_int = 1;
            if (wv != 0u && wv != 0x3F800000u) not_flt = 1;
        }
        if (__ballot_sync(0xffffffffu, not_int) && (threadIdx.x & 31) == 0)
            atomicOr(&g_flags[0], 1);
        if (__ballot_sync(0xffffffffu, not_flt) && (threadIdx.x & 31) == 0)
            atomicOr(&g_flags[1], 1);
    }
}

__device__ __forceinline__ float get_mask(const void* m, int idx, int mode) {
    if (mode == 1) return ((const int*)m)[idx] ? 1.0f : 0.0f;
    if (mode == 2) return ((const float*)m)[idx];
    return ((const unsigned char*)m)[idx] ? 1.0f : 0.0f;
}

__device__ __forceinline__ uint32_t smem_u32(const void* p) {
    uint32_t a;
    asm("{ .reg .u64 t; cvta.to.shared.u64 t, %1; cvt.u32.u64 %0, t; }" : "=r"(a) : "l"(p));
    return a;
}
__device__ __forceinline__ void cp16(uint32_t dst, const void* src) {
    asm volatile("cp.async.cg.shared.global [%0], [%1], 16;" :: "r"(dst), "l"(src));
}
#define CP_COMMIT() asm volatile("cp.async.commit_group;" ::: "memory")
#define CP_WAIT0()  asm volatile("cp.async.wait_group 0;" ::: "memory")

__device__ __forceinline__ void ldsm4(uint32_t r[4], uint32_t a) {
    asm volatile("ldmatrix.sync.aligned.m8n8.x4.shared.b16 {%0,%1,%2,%3}, [%4];"
                 : "=r"(r[0]), "=r"(r[1]), "=r"(r[2]), "=r"(r[3]) : "r"(a));
}
__device__ __forceinline__ void ldsm4t(uint32_t r[4], uint32_t a) {
    asm volatile("ldmatrix.sync.aligned.m8n8.x4.trans.shared.b16 {%0,%1,%2,%3}, [%4];"
                 : "=r"(r[0]), "=r"(r[1]), "=r"(r[2]), "=r"(r[3]) : "r"(a));
}
__device__ __forceinline__ void mma_f16(float d[4], uint32_t a0, uint32_t a1,
                                        uint32_t a2, uint32_t a3,
                                        uint32_t b0, uint32_t b1) {
    asm volatile(
        "mma.sync.aligned.m16n8k16.row.col.f32.f16.f16.f32 "
        "{%0,%1,%2,%3}, {%4,%5,%6,%7}, {%8,%9}, {%0,%1,%2,%3};"
        : "+f"(d[0]), "+f"(d[1]), "+f"(d[2]), "+f"(d[3])
        : "r"(a0), "r"(a1), "r"(a2), "r"(a3), "r"(b0), "r"(b1));
}
__device__ __forceinline__ float ex2f(float v) {
    float r;
    asm("ex2.approx.ftz.f32 %0, %1;" : "=f"(r) : "f"(v));
    return r;
}

// ---------------------------------------------------------------- main kernel
__global__ __launch_bounds__(256, 2)
void attn_mma(const void* __restrict__ mask, float* __restrict__ out) {
    extern __shared__ char sm[];
    const uint32_t sb = smem_u32(sm);

    const int tid  = threadIdx.x;
    const int w    = tid >> 5, lane = tid & 31;
    const int qrow = lane >> 2;       // 0..7
    const int qk   = lane & 3;        // 0..3
    const int arow0 = w * 16;         // this warp's 16-row band

    const int b  = blockIdx.y;
    const int i0 = blockIdx.x * TM;
    const int mode = (!g_flags[0]) ? 1 : ((!g_flags[1]) ? 2 : 0);
    const char* gx = (const char*)g_x16;     // fp16 x, 256B per row

    // ldmatrix lane-address offsets (bytes; per-ks/nb terms added at use)
    const int l7 = lane & 7, l8 = (lane >> 3) & 1, l16 = (lane >> 4) & 1;
    const uint32_t offA_xi = (uint32_t)((arow0 + l7 + 8 * l8) * PX + l16 * 16);
    const uint32_t offB_A  = (uint32_t)((l7 + 8 * l16) * PX + l8 * 16);
    const uint32_t offB_B  = (uint32_t)((l7 + 8 * l8) * PX + (8 * l16) * 2);

    float* sLM = (float*)(sm + SM_LM);

    // ---- stage Xi (cp.async) + tile-0 Xj + log-mask table ----
    {
        const int xr = tid >> 1;                          // 0..127
        const size_t srow = (size_t)(b * Tt + i0 + xr) * 256;
        #pragma unroll
        for (int i = 0; i < 8; i++) {
            const int ch = (tid & 1) + 2 * i;
            cp16(sb + SM_XI + xr * PX + ch * 16, gx + srow + ch * 16);
        }
        const int jr = tid >> 2;                          // 0..63
        const size_t jrow = (size_t)(b * Tt + jr) * 256;
        #pragma unroll
        for (int i = 0; i < 4; i++) {
            const int ch = (tid & 3) + 4 * i;
            cp16(sb + SM_XJ + jr * PX + ch * 16, gx + jrow + ch * 16);
        }
        CP_COMMIT();
    }
    #pragma unroll
    for (int e = 0; e < 4; e++) {
        const int t = tid + 256 * e;
        sLM[t] = (get_mask(mask, b * Tt + t, mode) != 0.0f) ? 0.0f : NEG_INF;
    }

    float acc[16][4];                 // O: 16 rows x 128 cols per warp
    #pragma unroll
    for (int nf = 0; nf < 16; nf++)
        #pragma unroll
        for (int c = 0; c < 4; c++) acc[nf][c] = 0.0f;
    float rsum[2] = {0.f, 0.f};       // rows qrow, qrow+8

    uint32_t pkp01[8], pkp23[8];      // P fragments (phase-B A-operand)
    const float qk2f = (float)(2 * qk);

    // prefetch tile jt+1 into buffer (jt+1)%3 (pure cp.async)
    auto prefetch = [&](int jt) {
        const uint32_t dst = sb + SM_XJ + ((jt + 1) % 3) * XJSZ;
        const int jr = tid >> 2;
        const size_t jrow = (size_t)(b * Tt + (jt + 1) * TN + jr) * 256;
        #pragma unroll
        for (int i = 0; i < 4; i++) {
            const int ch = (tid & 3) + 4 * i;
            cp16(dst + jr * PX + ch * 16, gx + jrow + ch * 16);
        }
        CP_COMMIT();
    };

    // phase A: S = Xi.Xj^T for tile jt (accumulators in s)
    auto phaseA = [&](int jt, float s[8][4]) {
        const uint32_t xjb = sb + SM_XJ + (jt % 3) * XJSZ;
        #pragma unroll
        for (int ks = 0; ks < Dd / 16; ++ks) {
            uint32_t a[4];
            ldsm4(a, sb + SM_XI + offA_xi + ks * 32);
            #pragma unroll
            for (int nb = 0; nb < 4; nb++) {
                uint32_t bb[4];
                ldsm4(bb, xjb + offB_A + nb * 16 * PX + ks * 32);
                mma_f16(s[2 * nb],     a[0], a[1], a[2], a[3], bb[0], bb[1]);
                mma_f16(s[2 * nb + 1], a[0], a[1], a[2], a[3], bb[2], bb[3]);
            }
        }
    };

    // epilogue: P = ex2(s*L2E + distL + lmL), block-uniform specialization;
    // writes packed fp16 OVER pkp (fully consumed by the preceding phase B).
    auto epilogue = [&](int jt, float s[8][4]) {
        const int j0 = jt * TN;
        const float* lmj = sLM + j0;
        if (j0 <= i0 - 73) {
            // dist == 10 for every element of this tile (block-wide)
            #pragma unroll
            for (int nf = 0; nf < 8; nf++) {
                const float2 lm = *(const float2*)(lmj + nf * 8 + 2 * qk);
                const float c0 = lm.x + C10, c1 = lm.y + C10;
                float p0 = ex2f(fmaf(s[nf][0], L2E, c0));
                float p1 = ex2f(fmaf(s[nf][1], L2E, c1));
                float p2 = ex2f(fmaf(s[nf][2], L2E, c0));
                float p3 = ex2f(fmaf(s[nf][3], L2E, c1));
                rsum[0] += p0 + p1;
                rsum[1] += p2 + p3;
                __half2 h01 = __floats2half2_rn(p0, p1);
                __half2 h23 = __floats2half2_rn(p2, p3);
                pkp01[nf] = *(const uint32_t*)&h01;
                pkp23[nf] = *(const uint32_t*)&h23;
            }
        } else if (j0 >= i0 + 117) {
            // dist = i - j everywhere (block-wide): no clamp needed
            const float fqL = ((float)(i0 + arow0 + qrow - j0) - qk2f) * L2E;
            #pragma unroll
            for (int nf = 0; nf < 8; nf++) {
                const float2 lm = *(const float2*)(lmj + nf * 8 + 2 * qk);
                const float dL = fqL - (float)(nf * 8) * L2E;
                const float a0 = dL + lm.x,             a1 = dL - L2E + lm.y;
                const float a2 = dL + 8.f * L2E + lm.x, a3 = dL + 7.f * L2E + lm.y;
                float p0 = ex2f(fmaf(s[nf][0], L2E, a0));
                float p1 = ex2f(fmaf(s[nf][1], L2E, a1));
                float p2 = ex2f(fmaf(s[nf][2], L2E, a2));
                float p3 = ex2f(fmaf(s[nf][3], L2E, a3));
                rsum[0] += p0 + p1;
                rsum[1] += p2 + p3;
                __half2 h01 = __floats2half2_rn(p0, p1);
                __half2 h23 = __floats2half2_rn(p2, p3);
                pkp01[nf] = *(const uint32_t*)&h01;
                pkp23[nf] = *(const uint32_t*)&h23;
            }
        } else {
            // general: dist = min(i-j, 10), computed in the log2 domain
            const float fqL = ((float)(i0 + arow0 + qrow - j0) - qk2f) * L2E;
            #pragma unroll
            for (int nf = 0; nf < 8; nf++) {
                const float2 lm = *(const float2*)(lmj + nf * 8 + 2 * qk);
                const float dL = fqL - (float)(nf * 8) * L2E;
                const float m0 = fminf(dL,             C10) + lm.x;
                const float m1 = fminf(dL - L2E,       C10) + lm.y;
                const float m2 = fminf(dL + 8.f * L2E, C10) + lm.x;
                const float m3 = fminf(dL + 7.f * L2E, C10) + lm.y;
                float p0 = ex2f(fmaf(s[nf][0], L2E, m0));
                float p1 = ex2f(fmaf(s[nf][1], L2E, m1));
                float p2 = ex2f(fmaf(s[nf][2], L2E, m2));
                float p3 = ex2f(fmaf(s[nf][3], L2E, m3));
                rsum[0] += p0 + p1;
                rsum[1] += p2 + p3;
                __half2 h01 = __floats2half2_rn(p0, p1);
                __half2 h23 = __floats2half2_rn(p2, p3);
                pkp01[nf] = *(const uint32_t*)&h01;
                pkp23[nf] = *(const uint32_t*)&h23;
            }
        }
    };

    // phase B: O += P(prev tile) . Xj(prev tile); A-operand from pk registers
    auto phaseB = [&](int jtprev) {
        const uint32_t xjb = sb + SM_XJ + (jtprev % 3) * XJSZ;
        #pragma unroll
        for (int ks = 0; ks < TN / 16; ++ks) {
            const uint32_t a0 = pkp01[2 * ks], a1 = pkp23[2 * ks];
            const uint32_t a2 = pkp01[2 * ks + 1], a3 = pkp23[2 * ks + 1];
            #pragma unroll
            for (int nb = 0; nb < 8; nb++) {
                uint32_t bb[4];
                ldsm4t(bb, xjb + offB_B + nb * 32 + ks * 16 * PX);
                mma_f16(acc[2 * nb],     a0, a1, a2, a3, bb[0], bb[1]);
                mma_f16(acc[2 * nb + 1], a0, a1, a2, a3, bb[2], bb[3]);
            }
        }
    };

    // ---- pipelined main loop ----
    CP_WAIT0();
    __syncthreads();
    prefetch(0);
    {
        float s[8][4];
        #pragma unroll
        for (int nf = 0; nf < 8; nf++)
            #pragma unroll
            for (int c = 0; c < 4; c++) s[nf][c] = 0.0f;
        phaseA(0, s);
        epilogue(0, s);
    }

    for (int jt = 1; jt < NJT; ++jt) {
        CP_WAIT0();
        __syncthreads();   // buf jt ready; everyone done with buf (jt+1)%3 == (jt-2)%3
        if (jt + 1 < NJT) prefetch(jt);

        phaseB(jt - 1);    // consumes pkp

        float s[8][4];
        #pragma unroll
        for (int nf = 0; nf < 8; nf++)
            #pragma unroll
            for (int c = 0; c < 4; c++) s[nf][c] = 0.0f;
        phaseA(jt, s);
        epilogue(jt, s);   // overwrites pkp in place
    }
    phaseB(NJT - 1);       // drain

    // ---- row-sum reduction + inverse (each row owned by exactly one warp) ----
    float* sRP  = (float*)(sm + SM_RP);
    float* sInv = (float*)(sm + SM_INV);
    #pragma unroll
    for (int rh = 0; rh < 2; rh++) {
        float v = rsum[rh];
        v += __shfl_xor_sync(0xffffffffu, v, 1);
        v += __shfl_xor_sync(0xffffffffu, v, 2);
        if (qk == 0) sRP[arow0 + rh * 8 + qrow] = v;
    }
    __syncthreads();
    if (tid < TM)
        sInv[tid] = ((sLM[i0 + tid] == 0.0f) ? 1.0f : 0.0f) / (sRP[tid] + EPSF);
    __syncthreads();

    // ---- write O ----
    {
        const int rl0 = arow0 + qrow;
        const float inv0 = sInv[rl0], inv1 = sInv[rl0 + 8];
        float* o0 = out + ((size_t)b * Tt + i0 + rl0) * Dd;
        float* o1 = o0 + 8 * Dd;
        #pragma unroll
        for (int nf = 0; nf < 16; nf++) {
            const int cl = nf * 8 + 2 * qk;
            *(float2*)(o0 + cl) = make_float2(acc[nf][0] * inv0, acc[nf][1] * inv0);
            *(float2*)(o1 + cl) = make_float2(acc[nf][2] * inv1, acc[nf][3] * inv1);
        }
    }
}

extern "C" void kernel_launch(void* const* d_in, const int* in_sizes, int n_in,
                              void* d_out, int out_size) {
    const float* x   = (const float*)d_in[0];
    const void* mask = d_in[1];
    float* out       = (float*)d_out;

    cudaFuncSetAttribute(attn_mma, cudaFuncAttributeMaxDynamicSharedMemorySize, SMEM_BYTES);

    cvt16_detect_kernel<<<(Bb * Tt * Dd / 8) / 256, 256>>>(
        (const float4*)x, (const unsigned int*)mask);
    dim3 grid(Tt / TM, Bb);
    attn_mma<<<grid, 256, SMEM_BYTES>>>(mask, out);
}